// round 14
// baseline (speedup 1.0000x reference)
#include <cuda_runtime.h>
#include <cuda_bf16.h>
#include <math.h>
#include <stdint.h>

#define CD 1024
#define LD 80
#define WDIM 300
#define WPAD 320
#define HW 196
#define BT 4
#define NP 784
#define OD 2048
#define NR (BT*LD)
#define NE (NR*CD)

#define MODE_NONE 0
#define MODE_ZRH  1
#define MODE_GRU2 2
#define MODE_TANH 3

#define TM 64
#define NOMASK 0x7FFFFFFF

// ---------------- fp32 scratch ----------------
__device__ float d_fwd[LD*CD];
__device__ float d_v[CD];
__device__ float d_c0p[CD];
__device__ float d_ball[3*CD];
__device__ float d_fwh[NP*CD];
__device__ float d_coeff[NP*LD];
__device__ float d_nodes[NE];
__device__ float d_zbuf[NE];
__device__ float d_hbuf[NE];

// ---------------- bf16 hi/lo operand buffers ----------------
__device__ unsigned short c_img_h[NP*CD],    c_img_l[NP*CD];
__device__ unsigned short c_fc1_h[CD*CD],    c_fc1_l[CD*CD];
__device__ unsigned short c_wemb_h[LD*WPAD], c_wemb_l[LD*WPAD];
__device__ unsigned short c_fc2_h[CD*WPAD],  c_fc2_l[CD*WPAD];
__device__ unsigned short c_wall_h[3*CD*CD], c_wall_l[3*CD*CD];
__device__ unsigned short c_u3_h[CD*CD],     c_u3_l[CD*CD];
__device__ unsigned short c_u5_h[CD*CD],     c_u5_l[CD*CD];
__device__ unsigned short c_fco_h[OD*2*CD],  c_fco_l[OD*2*CD];
__device__ unsigned short c_nodes_h[NE],     c_nodes_l[NE];
__device__ unsigned short c_a_h[NE],         c_a_l[NE];
__device__ unsigned short c_rn_h[NE],        c_rn_l[NE];
__device__ unsigned short c_g_h[NE],         c_g_l[NE];

// ---------------- helpers ----------------
__device__ __forceinline__ uint32_t smem_to_u32(const void* p) {
    uint32_t a;
    asm("{ .reg .u64 t; cvta.to.shared.u64 t, %1; cvt.u32.u64 %0, t; }" : "=r"(a) : "l"(p));
    return a;
}
__device__ __forceinline__ float tanha(float x) {
    float t;
    asm("tanh.approx.f32 %0, %1;" : "=f"(t) : "f"(x));
    return t;
}
__device__ __forceinline__ float sigf(float x) {
    return __fdividef(1.f, 1.f + __expf(-x));
}
__device__ __forceinline__ void split_bf(float v, unsigned short* h, unsigned short* l) {
    __nv_bfloat16 hb = __float2bfloat16(v);
    *h = __bfloat16_as_ushort(hb);
    *l = __bfloat16_as_ushort(__float2bfloat16(v - __bfloat162float(hb)));
}
__device__ __forceinline__ void split4(float4 v,
                                       unsigned short* hbase, unsigned short* lbase, int e) {
    __nv_bfloat16 h0 = __float2bfloat16(v.x), h1 = __float2bfloat16(v.y);
    __nv_bfloat16 h2 = __float2bfloat16(v.z), h3 = __float2bfloat16(v.w);
    float l0 = v.x - __bfloat162float(h0), l1 = v.y - __bfloat162float(h1);
    float l2 = v.z - __bfloat162float(h2), l3 = v.w - __bfloat162float(h3);
    uint2 hp, lp;
    hp.x = (uint32_t)__bfloat16_as_ushort(h0) | ((uint32_t)__bfloat16_as_ushort(h1) << 16);
    hp.y = (uint32_t)__bfloat16_as_ushort(h2) | ((uint32_t)__bfloat16_as_ushort(h3) << 16);
    lp.x = (uint32_t)__bfloat16_as_ushort(__float2bfloat16(l0)) |
           ((uint32_t)__bfloat16_as_ushort(__float2bfloat16(l1)) << 16);
    lp.y = (uint32_t)__bfloat16_as_ushort(__float2bfloat16(l2)) |
           ((uint32_t)__bfloat16_as_ushort(__float2bfloat16(l3)) << 16);
    *(uint2*)&hbase[e] = hp;
    *(uint2*)&lbase[e] = lp;
}
__device__ __forceinline__ void ldsm_x4(uint32_t* r, uint32_t addr) {
    asm volatile("ldmatrix.sync.aligned.m8n8.x4.shared.b16 {%0,%1,%2,%3}, [%4];"
        : "=r"(r[0]), "=r"(r[1]), "=r"(r[2]), "=r"(r[3]) : "r"(addr));
}
__device__ __forceinline__ void mma16816(float* c, const uint32_t* a, const uint32_t* b) {
    asm volatile("mma.sync.aligned.m16n8k16.row.col.f32.bf16.bf16.f32 "
        "{%0,%1,%2,%3}, {%4,%5,%6,%7}, {%8,%9}, {%0,%1,%2,%3};"
        : "+f"(c[0]), "+f"(c[1]), "+f"(c[2]), "+f"(c[3])
        : "r"(a[0]), "r"(a[1]), "r"(a[2]), "r"(a[3]), "r"(b[0]), "r"(b[1]));
}
__device__ __forceinline__ void cpasync16(uint32_t dst, const void* src, bool ok) {
    asm volatile("cp.async.cg.shared.global [%0], [%1], 16, %2;"
        :: "r"(dst), "l"(src), "r"(ok ? 16 : 0) : "memory");
}
__device__ __forceinline__ void cp_commit() {
    asm volatile("cp.async.commit_group;" ::: "memory");
}
template<int N> __device__ __forceinline__ void cp_waitN() {
    asm volatile("cp.async.wait_group %0;" :: "n"(N) : "memory");
}
__device__ __forceinline__ uint32_t sw64(uint32_t off) {
    return off ^ ((off >> 3) & 0x30);
}

// ---------------- merged prep ----------------
__global__ void k_prep(const float* __restrict__ fc1, const float* __restrict__ img,
                       const float* __restrict__ wemb, const float* __restrict__ fc2,
                       const float* __restrict__ u3, const float* __restrict__ u5,
                       const float* __restrict__ fco,
                       const float* __restrict__ w3, const float* __restrict__ w4,
                       const float* __restrict__ w5,
                       const float* __restrict__ b3, const float* __restrict__ u3b,
                       const float* __restrict__ b4, const float* __restrict__ b5,
                       const float* __restrict__ u5b,
                       const float* __restrict__ fc3, const float* __restrict__ fca,
                       const float* __restrict__ fc3b) {
    const int q1 = CD*CD/4;
    const int q2 = q1 + NP*CD/4;
    const int q3 = q2 + LD*WPAD/4;
    const int q4 = q3 + CD*WPAD/4;
    const int q5 = q4 + CD*CD/4;
    const int q6 = q5 + CD*CD/4;
    const int q7 = q6 + OD*2*CD/4;
    const int q8 = q7 + 3*CD*CD/4;
    const int q9 = q8 + 3*CD;
    const int q10 = q9 + CD;
    const int q11 = q10 + CD;
    int stride = gridDim.x*blockDim.x;
    for (int i = blockIdx.x*blockDim.x + threadIdx.x; i < q11; i += stride) {
        if (i < q1) {
            int e = 4*i;
            split4(*(const float4*)&fc1[e], c_fc1_h, c_fc1_l, e);
        } else if (i < q2) {
            int e = 4*(i - q1);
            split4(*(const float4*)&img[e], c_img_h, c_img_l, e);
        } else if (i < q3) {
            int e = 4*(i - q2);
            int r = e / WPAD, c = e - r*WPAD;
            float4 v = (c < WDIM) ? *(const float4*)&wemb[r*WDIM + c]
                                  : make_float4(0.f, 0.f, 0.f, 0.f);
            split4(v, c_wemb_h, c_wemb_l, e);
        } else if (i < q4) {
            int e = 4*(i - q3);
            int r = e / WPAD, c = e - r*WPAD;
            float4 v = (c < WDIM) ? *(const float4*)&fc2[r*WDIM + c]
                                  : make_float4(0.f, 0.f, 0.f, 0.f);
            split4(v, c_fc2_h, c_fc2_l, e);
        } else if (i < q5) {
            int e = 4*(i - q4);
            split4(*(const float4*)&u3[e], c_u3_h, c_u3_l, e);
        } else if (i < q6) {
            int e = 4*(i - q5);
            split4(*(const float4*)&u5[e], c_u5_h, c_u5_l, e);
        } else if (i < q7) {
            int e = 4*(i - q6);
            split4(*(const float4*)&fco[e], c_fco_h, c_fco_l, e);
        } else if (i < q8) {
            int e = 4*(i - q7);
            int which = e / (CD*CD);
            int rem = e - which*(CD*CD);
            int r = rem >> 10, c = rem & (CD-1);
            const float* w = (which==0) ? w3 : (which==1) ? w4 : w5;
            float4 a = *(const float4*)&w[r*2*CD + c];
            float4 b = *(const float4*)&w[r*2*CD + CD + c];
            split4(make_float4(a.x+b.x, a.y+b.y, a.z+b.z, a.w+b.w),
                   c_wall_h, c_wall_l, e);
        } else if (i < q9) {
            int j = i - q8;
            int which = j >> 10, c = j & (CD-1);
            if (which == 0)      d_ball[c]        = b3[c] + u3b[c];
            else if (which == 1) d_ball[CD + c]   = b4[c] + u3b[c]; // torch bug kept
            else                 d_ball[2*CD + c] = b5[c] + u5b[c];
        } else if (i < q10) {
            int c = i - q9;
            float acc = 0.f;
            #pragma unroll 8
            for (int j = 0; j < CD; ++j) acc += fca[j] * fc3[j*CD + c];
            d_v[c] = acc;
        } else {
            int j = i - q10;
            d_c0p[j] = fc3b[j] * fca[j];
        }
    }
}

// ---------------- tensor GEMM: 256 threads, warp-split-K, 4-stage cp.async ring ------
// C = epi( A@B^T [+ A2@B2^T] + bias ); fp32 via bf16 split (hh + hl + lh).
// Warp-group wg=0 (warps 0-3) computes k[0,16) of each k32 stage; wg=1 computes
// k[16,32). Separate accumulators, smem-reduced after the mainloop; group 0 runs
// the epilogue. Doubles warps/SMSP at identical tile geometry.
template<int MODE, int TNN>
__global__ __launch_bounds__(256) void t_gemm(
    const unsigned short* __restrict__ Ah, const unsigned short* __restrict__ Al, int lda,
    const unsigned short* __restrict__ Bh, const unsigned short* __restrict__ Bl, int ldb,
    const unsigned short* __restrict__ A2h, const unsigned short* __restrict__ A2l, int lda2,
    const unsigned short* __restrict__ B2h, const unsigned short* __restrict__ B2l, int ldb2,
    int b2mask, int n2_limit,
    int M, int N, int Kpad,
    const float* __restrict__ bias,
    float* __restrict__ p0, float* __restrict__ p1, float* __restrict__ p2,
    unsigned short* __restrict__ q0, unsigned short* __restrict__ q1,
    float* __restrict__ C, int ldc)
{
    constexpr int JF = TNN/16;
    constexpr int JH = JF/2;
    constexpr int STAGE = 8192 + TNN*128;
    constexpr int NCOPY = 512 + TNN*8;     // per-stage 16B copies (A 512 + B 2*TNN*4)
    __shared__ __align__(128) char dsm[4*STAGE];
    uint32_t sbase = smem_to_u32(dsm);

    const int tid = threadIdx.x;
    const int wid = tid >> 5;
    const int lane = tid & 31;
    const int wg = wid >> 2;               // k-split group
    const int w4 = wid & 3;
    const int m0 = blockIdx.y * TM;
    const int n0 = blockIdx.x * TNN;
    const int wm = (w4 >> 1) * 32;
    const int wn = (w4 & 1) * (TNN/2);
    const int kbase = wg * 16;

    const int qm = lane >> 3, rr = lane & 7;
    const int lrow = (qm & 1)*8 + rr;
    const int lkof = (qm >> 1)*8;

    float acc[2][JF][4];
    #pragma unroll
    for (int i = 0; i < 2; ++i)
        #pragma unroll
        for (int j = 0; j < JF; ++j)
            #pragma unroll
            for (int s = 0; s < 4; ++s) acc[i][j][s] = 0.f;

    const int nst1 = Kpad >> 5;
    const bool do2 = (A2h != nullptr) && (n0 < n2_limit);
    const int nst = do2 ? 2*nst1 : nst1;

    auto stage = [&](int t) {
        int pass = (t >= nst1) ? 1 : 0;
        int k0 = (t - pass*nst1) << 5;
        const unsigned short* pAh = pass ? A2h : Ah;
        const unsigned short* pAl = pass ? A2l : Al;
        const unsigned short* pBh = pass ? B2h : Bh;
        const unsigned short* pBl = pass ? B2l : Bl;
        int la = pass ? lda2 : lda;
        int lb = pass ? ldb2 : ldb;
        int bm = pass ? b2mask : NOMASK;
        uint32_t sb = sbase + (t & 3) * STAGE;
        #pragma unroll
        for (int qq = 0; qq*256 < NCOPY; ++qq) {
            int c = tid + (qq << 8);
            if (c >= NCOPY) break;
            if (c < 512) {
                int part = c >> 8;
                int sub = c & 255;
                int row = sub >> 2, quad = sub & 3;
                int gr = m0 + row;
                bool ok = gr < M;
                const unsigned short* s = (part ? pAl : pAh)
                                          + (size_t)(ok ? gr : 0)*la + k0 + quad*8;
                uint32_t off = sw64((uint32_t)(row*64 + quad*16));
                cpasync16(sb + part*4096 + off, s, ok);
            } else {
                int cb = c - 512;
                int part = (cb >= TNN*4) ? 1 : 0;
                int sub = cb - part*(TNN*4);
                int row = sub >> 2, quad = sub & 3;
                int gn = n0 + row;
                bool ok = gn < N;
                int er = (ok ? gn : 0) & bm;
                const unsigned short* s = (part ? pBl : pBh)
                                          + (size_t)er*lb + k0 + quad*8;
                uint32_t off = sw64((uint32_t)(row*64 + quad*16));
                cpasync16(sb + 8192 + part*(TNN*64) + off, s, ok);
            }
        }
        cp_commit();
    };

    stage(0);
    if (nst > 1) stage(1);
    if (nst > 2) stage(2);
    for (int t = 0; t < nst; ++t) {
        if (t + 2 < nst) cp_waitN<2>();
        else if (t + 1 < nst) cp_waitN<1>();
        else cp_waitN<0>();
        __syncthreads();
        uint32_t sb = sbase + (t & 3) * STAGE;
        uint32_t sa_hi = sb, sa_lo = sb + 4096;
        uint32_t sb_hi = sb + 8192, sb_lo = sb + 8192 + TNN*64;
        {
            const int k0 = kbase;          // this warp-group's half of the k32 chunk
            uint32_t ah[2][4], al[2][4], bh[JF][2], bl[JF][2];
            #pragma unroll
            for (int i = 0; i < 2; ++i) {
                uint32_t off = sw64((uint32_t)((wm + i*16 + lrow)*64 + (k0 + lkof)*2));
                ldsm_x4(ah[i], sa_hi + off);
                ldsm_x4(al[i], sa_lo + off);
            }
            #pragma unroll
            for (int jh = 0; jh < JH; ++jh) {
                uint32_t off = sw64((uint32_t)((wn + jh*16 + lrow)*64 + (k0 + lkof)*2));
                uint32_t r[4];
                ldsm_x4(r, sb_hi + off);
                bh[2*jh][0]=r[0]; bh[2*jh][1]=r[2]; bh[2*jh+1][0]=r[1]; bh[2*jh+1][1]=r[3];
                ldsm_x4(r, sb_lo + off);
                bl[2*jh][0]=r[0]; bl[2*jh][1]=r[2]; bl[2*jh+1][0]=r[1]; bl[2*jh+1][1]=r[3];
            }
            #pragma unroll
            for (int i = 0; i < 2; ++i)
                #pragma unroll
                for (int j = 0; j < JF; ++j) {
                    mma16816(acc[i][j], ah[i], bh[j]);
                    mma16816(acc[i][j], ah[i], bl[j]);
                    mma16816(acc[i][j], al[i], bh[j]);
                }
        }
        if (t + 3 < nst) stage(t + 3);
    }

    // cross-group accumulator reduction (reuse ring smem)
    __syncthreads();
    float* sred = (float*)dsm;
    if (wg == 1) {
        int base = (tid - 128) * 16;
        #pragma unroll
        for (int i = 0; i < 2; ++i)
            #pragma unroll
            for (int j = 0; j < JF; ++j)
                #pragma unroll
                for (int s = 0; s < 4; ++s)
                    sred[base + (i*JF + j)*4 + s] = acc[i][j][s];
    }
    __syncthreads();
    if (wg == 1) return;
    {
        int base = tid * 16;
        #pragma unroll
        for (int i = 0; i < 2; ++i)
            #pragma unroll
            for (int j = 0; j < JF; ++j)
                #pragma unroll
                for (int s = 0; s < 4; ++s)
                    acc[i][j][s] += sred[base + (i*JF + j)*4 + s];
    }

    // epilogue (group 0 only)
    const int g = lane >> 2, tq = (lane & 3)*2;
    #pragma unroll
    for (int i = 0; i < 2; ++i) {
        #pragma unroll
        for (int half = 0; half < 2; ++half) {
            int m = m0 + wm + i*16 + g + half*8;
            if (m >= M) continue;
            #pragma unroll
            for (int j = 0; j < JF; ++j) {
                #pragma unroll
                for (int s = 0; s < 2; ++s) {
                    int n = n0 + wn + j*8 + tq + s;
                    if (n >= N) continue;
                    float x = acc[i][j][half*2 + s];
                    if (MODE == MODE_NONE) {
                        C[(size_t)m*ldc + n] = x;
                    } else if (MODE == MODE_ZRH) {
                        x += bias[n];
                        if (n < CD) {
                            p0[m*CD + n] = sigf(x);
                        } else if (n < 2*CD) {
                            int nn = n - CD;
                            float rn = sigf(x) * p2[m*CD + nn];
                            split_bf(rn, &q0[m*CD + nn], &q1[m*CD + nn]);
                        } else {
                            p1[m*CD + (n - 2*CD)] = x;
                        }
                    } else if (MODE == MODE_GRU2) {
                        float hc = tanha(x + p1[m*CD + n]);
                        float z  = p0[m*CD + n];
                        float nv = (1.f - z)*p2[m*CD + n] + z*hc;
                        p2[m*CD + n] = nv;
                        split_bf(nv, &q0[m*CD + n], &q1[m*CD + n]);
                    } else { // MODE_TANH
                        C[(size_t)m*ldc + n] = tanha(x + bias[n]);
                    }
                }
            }
        }
    }
}

// ---------------- semantic-branch kernels ----------------
__global__ __launch_bounds__(256) void k_coeff(const float* __restrict__ fcab) {
    int n0 = blockIdx.x * 2;
    int warp = threadIdx.x >> 5, lane = threadIdx.x & 31;
    float fw0[32], fw1[32], v_r[32];
    const float* r0 = d_fwh + n0*CD + lane;
    #pragma unroll
    for (int q = 0; q < 32; ++q) {
        fw0[q] = r0[q*32];
        fw1[q] = r0[CD + q*32];
        v_r[q] = d_v[q*32 + lane];
    }
    float c0 = 0.f;
    #pragma unroll
    for (int q = 0; q < 32; ++q) c0 += d_c0p[q*32 + lane];
    #pragma unroll
    for (int o = 16; o > 0; o >>= 1) c0 += __shfl_xor_sync(0xffffffffu, c0, o);
    c0 += fcab[0];
    for (int l = warp; l < LD; l += 8) {
        const float* fw = d_fwd + l*CD + lane;
        float a0 = 0.f, a1 = 0.f;
        #pragma unroll
        for (int q = 0; q < 32; ++q) {
            float w = fw[q*32];
            float t0 = tanha(fw0[q] * w);
            float t1 = tanha(fw1[q] * w);
            a0 += t0 * v_r[q];
            a1 += t1 * v_r[q];
        }
        #pragma unroll
        for (int o = 16; o > 0; o >>= 1) {
            a0 += __shfl_xor_sync(0xffffffffu, a0, o);
            a1 += __shfl_xor_sync(0xffffffffu, a1, o);
        }
        if (lane == 0) {
            d_coeff[n0*LD + l]     = a0 + c0;
            d_coeff[(n0+1)*LD + l] = a1 + c0;
        }
    }
}

__global__ __launch_bounds__(256) void k_softmax() {
    int g = blockIdx.x*8 + (threadIdx.x >> 5);
    int lane = threadIdx.x & 31;
    if (g >= NP*LD/HW) return;
    float* p = d_coeff + g*HW;
    float vals[7];
    float mx = -1e30f;
    #pragma unroll
    for (int q = 0; q < 7; ++q) {
        int i = lane + q*32;
        vals[q] = (i < HW) ? p[i] : -1e30f;
        mx = fmaxf(mx, vals[q]);
    }
    #pragma unroll
    for (int o = 16; o > 0; o >>= 1) mx = fmaxf(mx, __shfl_xor_sync(0xffffffffu, mx, o));
    float s = 0.f;
    #pragma unroll
    for (int q = 0; q < 7; ++q) {
        int i = lane + q*32;
        if (i < HW) { vals[q] = __expf(vals[q] - mx); s += vals[q]; }
    }
    #pragma unroll
    for (int o = 16; o > 0; o >>= 1) s += __shfl_xor_sync(0xffffffffu, s, o);
    float inv = __fdividef(1.f, s);
    #pragma unroll
    for (int q = 0; q < 7; ++q) {
        int i = lane + q*32;
        if (i < HW) p[i] = vals[q]*inv;
    }
}

__global__ __launch_bounds__(256) void k_g(const float* __restrict__ img) {
    __shared__ float s[HW];
    int b = blockIdx.x / LD, l = blockIdx.x % LD;
    for (int tt = threadIdx.x; tt < HW; tt += 256)
        s[tt] = d_coeff[(b*HW + tt)*LD + l];
    __syncthreads();
    const float* xb = img + b*HW*CD;
    int c = threadIdx.x;
    float a0 = 0.f, a1 = 0.f, a2 = 0.f, a3 = 0.f;
    #pragma unroll 4
    for (int tt = 0; tt < HW; ++tt) {
        float w = s[tt];
        const float* xr = xb + tt*CD;
        a0 += w*xr[c]; a1 += w*xr[c+256]; a2 += w*xr[c+512]; a3 += w*xr[c+768];
    }
    int base = (b*LD + l)*CD + c;
    float vals[4] = {a0, a1, a2, a3};
    #pragma unroll
    for (int q = 0; q < 4; ++q) {
        int idx = base + q*256;
        d_nodes[idx] = vals[q];
        split_bf(vals[q], &c_g_h[idx], &c_g_l[idx]);
        c_nodes_h[idx] = c_g_h[idx];
        c_nodes_l[idx] = c_g_l[idx];
    }
}

__global__ __launch_bounds__(256) void k_a(const float* __restrict__ adj) {
    __shared__ float ar[LD];
    int b = blockIdx.x / LD, nn = blockIdx.x % LD;
    if (threadIdx.x < LD) ar[threadIdx.x] = adj[nn*LD + threadIdx.x];
    __syncthreads();
    int c = threadIdx.x;
    const float* nb = d_nodes + b*LD*CD;
    float a0 = 0.f, a1 = 0.f, a2 = 0.f, a3 = 0.f;
    #pragma unroll 4
    for (int m = 0; m < LD; ++m) {
        float w = ar[m];
        const float* nr = nb + m*CD;
        a0 += w*nr[c]; a1 += w*nr[c+256]; a2 += w*nr[c+512]; a3 += w*nr[c+768];
    }
    int base = (b*LD + nn)*CD + c;
    float vals[4] = {a0, a1, a2, a3};
    #pragma unroll
    for (int q = 0; q < 4; ++q) {
        int idx = base + q*256;
        split_bf(vals[q], &c_a_h[idx], &c_a_l[idx]);
    }
}

// ---------------- host ----------------
struct Sym {
    float *fwd, *v, *c0p, *ball, *fwh, *coeff, *nodes, *zbuf, *hbuf;
    unsigned short *imgh, *imgl, *fc1h, *fc1l, *wembh, *wembl, *fc2h, *fc2l;
    unsigned short *wallh, *walll, *u3h, *u3l, *u5h, *u5l, *fcoh, *fcol;
    unsigned short *ndh, *ndl, *ah, *al, *rnh, *rnl, *gh, *gl;
};
static void get_syms(Sym& S) {
    cudaGetSymbolAddress((void**)&S.fwd, d_fwd);
    cudaGetSymbolAddress((void**)&S.v, d_v);
    cudaGetSymbolAddress((void**)&S.c0p, d_c0p);
    cudaGetSymbolAddress((void**)&S.ball, d_ball);
    cudaGetSymbolAddress((void**)&S.fwh, d_fwh);
    cudaGetSymbolAddress((void**)&S.coeff, d_coeff);
    cudaGetSymbolAddress((void**)&S.nodes, d_nodes);
    cudaGetSymbolAddress((void**)&S.zbuf, d_zbuf);
    cudaGetSymbolAddress((void**)&S.hbuf, d_hbuf);
    cudaGetSymbolAddress((void**)&S.imgh, c_img_h);   cudaGetSymbolAddress((void**)&S.imgl, c_img_l);
    cudaGetSymbolAddress((void**)&S.fc1h, c_fc1_h);   cudaGetSymbolAddress((void**)&S.fc1l, c_fc1_l);
    cudaGetSymbolAddress((void**)&S.wembh, c_wemb_h); cudaGetSymbolAddress((void**)&S.wembl, c_wemb_l);
    cudaGetSymbolAddress((void**)&S.fc2h, c_fc2_h);   cudaGetSymbolAddress((void**)&S.fc2l, c_fc2_l);
    cudaGetSymbolAddress((void**)&S.wallh, c_wall_h); cudaGetSymbolAddress((void**)&S.walll, c_wall_l);
    cudaGetSymbolAddress((void**)&S.u3h, c_u3_h);     cudaGetSymbolAddress((void**)&S.u3l, c_u3_l);
    cudaGetSymbolAddress((void**)&S.u5h, c_u5_h);     cudaGetSymbolAddress((void**)&S.u5l, c_u5_l);
    cudaGetSymbolAddress((void**)&S.fcoh, c_fco_h);   cudaGetSymbolAddress((void**)&S.fcol, c_fco_l);
    cudaGetSymbolAddress((void**)&S.ndh, c_nodes_h);  cudaGetSymbolAddress((void**)&S.ndl, c_nodes_l);
    cudaGetSymbolAddress((void**)&S.ah, c_a_h);       cudaGetSymbolAddress((void**)&S.al, c_a_l);
    cudaGetSymbolAddress((void**)&S.rnh, c_rn_h);     cudaGetSymbolAddress((void**)&S.rnl, c_rn_l);
    cudaGetSymbolAddress((void**)&S.gh, c_g_h);       cudaGetSymbolAddress((void**)&S.gl, c_g_l);
}

template<int MODE, int TNN>
static void tg(const unsigned short* Ah, const unsigned short* Al, int lda,
               const unsigned short* Bh, const unsigned short* Bl, int ldb,
               const unsigned short* A2h, const unsigned short* A2l, int lda2,
               const unsigned short* B2h, const unsigned short* B2l, int ldb2,
               int b2mask, int n2lim, int M, int N, int Kpad,
               const float* bias, float* p0, float* p1, float* p2,
               unsigned short* q0, unsigned short* q1, float* C, int ldc) {
    dim3 grid((N + TNN - 1)/TNN, (M + TM - 1)/TM);
    t_gemm<MODE, TNN><<<grid, 256>>>(Ah, Al, lda, Bh, Bl, ldb, A2h, A2l, lda2,
                                     B2h, B2l, ldb2, b2mask, n2lim, M, N, Kpad,
                                     bias, p0, p1, p2, q0, q1, C, ldc);
}

extern "C" void kernel_launch(void* const* d_in, const int* in_sizes, int n_in,
                              void* d_out, int out_size) {
    const float* img  = (const float*)d_in[0];
    const float* wemb = (const float*)d_in[1];
    const float* adj  = (const float*)d_in[2];
    const float* fc1  = (const float*)d_in[3];
    const float* fc2  = (const float*)d_in[4];
    const float* fc3  = (const float*)d_in[5];
    const float* fc3b = (const float*)d_in[6];
    const float* fca  = (const float*)d_in[7];
    const float* fcab = (const float*)d_in[8];
    const float* w3   = (const float*)d_in[9];
    const float* b3   = (const float*)d_in[10];
    const float* u3   = (const float*)d_in[11];
    const float* u3b  = (const float*)d_in[12];
    const float* w4   = (const float*)d_in[13];
    const float* b4   = (const float*)d_in[14];
    const float* w5   = (const float*)d_in[15];
    const float* b5   = (const float*)d_in[16];
    const float* u5   = (const float*)d_in[17];
    const float* u5b  = (const float*)d_in[18];
    const float* fco  = (const float*)d_in[19];
    const float* fcob = (const float*)d_in[20];
    float* out = (float*)d_out;

    Sym S; get_syms(S);

    // 1: all prep
    k_prep<<<2048, 256>>>(fc1, img, wemb, fc2, u3, u5, fco,
                          w3, w4, w5, b3, u3b, b4, b5, u5b, fc3, fca, fc3b);
    // 2: f_wd = wemb @ fc2^T
    tg<MODE_NONE, 32>(S.wembh, S.wembl, WPAD, S.fc2h, S.fc2l, WPAD,
                      nullptr, nullptr, 0, nullptr, nullptr, 0, NOMASK, 0,
                      LD, CD, WPAD, nullptr, nullptr, nullptr, nullptr, nullptr, nullptr,
                      S.fwd, CD);
    // 3: f_wh = x @ fc1^T
    tg<MODE_NONE, 32>(S.imgh, S.imgl, CD, S.fc1h, S.fc1l, CD,
                      nullptr, nullptr, 0, nullptr, nullptr, 0, NOMASK, 0,
                      NP, CD, CD, nullptr, nullptr, nullptr, nullptr, nullptr, nullptr,
                      S.fwh, CD);
    // 4-6: semantic chain
    k_coeff<<<NP/2, 256>>>(fcab);
    k_softmax<<<40, 256>>>();
    k_g<<<BT*LD, 256>>>(img);

    // GGNN
    for (int step = 0; step < 3; ++step) {
        k_a<<<BT*LD, 256>>>(adj);
        tg<MODE_ZRH, 32>(S.ah, S.al, CD, S.wallh, S.walll, CD,
                         S.ndh, S.ndl, CD, S.u3h, S.u3l, CD, CD-1, 2*CD,
                         NR, 3*CD, CD, S.ball, S.zbuf, S.hbuf, S.nodes,
                         S.rnh, S.rnl, nullptr, 0);
        tg<MODE_GRU2, 32>(S.rnh, S.rnl, CD, S.u5h, S.u5l, CD,
                          nullptr, nullptr, 0, nullptr, nullptr, 0, NOMASK, 0,
                          NR, CD, CD, nullptr, S.zbuf, S.hbuf, S.nodes,
                          S.ndh, S.ndl, nullptr, 0);
    }

    // out = tanh([nodes, g] @ fco^T + fco_b): dual-K over fco column halves
    tg<MODE_TANH, 32>(S.ndh, S.ndl, CD, S.fcoh, S.fcol, 2*CD,
                      S.gh, S.gl, CD, S.fcoh + CD, S.fcol + CD, 2*CD, NOMASK, NOMASK,
                      NR, OD, CD, fcob, nullptr, nullptr, nullptr, nullptr, nullptr,
                      out, OD);
}

// round 15
// speedup vs baseline: 1.0952x; 1.0952x over previous
#include <cuda_runtime.h>
#include <cuda_bf16.h>
#include <math.h>
#include <stdint.h>

#define CD 1024
#define LD 80
#define WDIM 300
#define WPAD 320
#define HW 196
#define BT 4
#define NP 784
#define OD 2048
#define NR (BT*LD)
#define NE (NR*CD)

#define MODE_NONE 0
#define MODE_ZRH  1
#define MODE_GRU2 2
#define MODE_TANH 3

#define TM 64
#define NOMASK 0x7FFFFFFF

// ---------------- fp32 scratch ----------------
__device__ float d_fwd[LD*CD];
__device__ float d_v[CD];
__device__ float d_c0p[CD];
__device__ float d_ball[3*CD];
__device__ float d_fwh[NP*CD];
__device__ float d_coeff[NP*LD];
__device__ float d_nodes[NE];
__device__ float d_zbuf[NE];
__device__ float d_hbuf[NE];

// ---------------- bf16 hi/lo operand buffers ----------------
__device__ unsigned short c_img_h[NP*CD],    c_img_l[NP*CD];
__device__ unsigned short c_fc1_h[CD*CD],    c_fc1_l[CD*CD];
__device__ unsigned short c_wemb_h[LD*WPAD], c_wemb_l[LD*WPAD];
__device__ unsigned short c_fc2_h[CD*WPAD],  c_fc2_l[CD*WPAD];
__device__ unsigned short c_wall_h[3*CD*CD], c_wall_l[3*CD*CD];
__device__ unsigned short c_u3_h[CD*CD],     c_u3_l[CD*CD];
__device__ unsigned short c_u5_h[CD*CD],     c_u5_l[CD*CD];
__device__ unsigned short c_fco_h[OD*2*CD],  c_fco_l[OD*2*CD];
__device__ unsigned short c_nodes_h[NE],     c_nodes_l[NE];
__device__ unsigned short c_a_h[NE],         c_a_l[NE];
__device__ unsigned short c_rn_h[NE],        c_rn_l[NE];
__device__ unsigned short c_g_h[NE],         c_g_l[NE];

// ---------------- helpers ----------------
__device__ __forceinline__ uint32_t smem_to_u32(const void* p) {
    uint32_t a;
    asm("{ .reg .u64 t; cvta.to.shared.u64 t, %1; cvt.u32.u64 %0, t; }" : "=r"(a) : "l"(p));
    return a;
}
__device__ __forceinline__ float tanha(float x) {
    float t;
    asm("tanh.approx.f32 %0, %1;" : "=f"(t) : "f"(x));
    return t;
}
__device__ __forceinline__ float sigf(float x) {
    return __fdividef(1.f, 1.f + __expf(-x));
}
__device__ __forceinline__ void split_bf(float v, unsigned short* h, unsigned short* l) {
    __nv_bfloat16 hb = __float2bfloat16(v);
    *h = __bfloat16_as_ushort(hb);
    *l = __bfloat16_as_ushort(__float2bfloat16(v - __bfloat162float(hb)));
}
__device__ __forceinline__ void split4(float4 v,
                                       unsigned short* hbase, unsigned short* lbase, int e) {
    __nv_bfloat16 h0 = __float2bfloat16(v.x), h1 = __float2bfloat16(v.y);
    __nv_bfloat16 h2 = __float2bfloat16(v.z), h3 = __float2bfloat16(v.w);
    float l0 = v.x - __bfloat162float(h0), l1 = v.y - __bfloat162float(h1);
    float l2 = v.z - __bfloat162float(h2), l3 = v.w - __bfloat162float(h3);
    uint2 hp, lp;
    hp.x = (uint32_t)__bfloat16_as_ushort(h0) | ((uint32_t)__bfloat16_as_ushort(h1) << 16);
    hp.y = (uint32_t)__bfloat16_as_ushort(h2) | ((uint32_t)__bfloat16_as_ushort(h3) << 16);
    lp.x = (uint32_t)__bfloat16_as_ushort(__float2bfloat16(l0)) |
           ((uint32_t)__bfloat16_as_ushort(__float2bfloat16(l1)) << 16);
    lp.y = (uint32_t)__bfloat16_as_ushort(__float2bfloat16(l2)) |
           ((uint32_t)__bfloat16_as_ushort(__float2bfloat16(l3)) << 16);
    *(uint2*)&hbase[e] = hp;
    *(uint2*)&lbase[e] = lp;
}
__device__ __forceinline__ void ldsm_x4(uint32_t* r, uint32_t addr) {
    asm volatile("ldmatrix.sync.aligned.m8n8.x4.shared.b16 {%0,%1,%2,%3}, [%4];"
        : "=r"(r[0]), "=r"(r[1]), "=r"(r[2]), "=r"(r[3]) : "r"(addr));
}
__device__ __forceinline__ void mma16816(float* c, const uint32_t* a, const uint32_t* b) {
    asm volatile("mma.sync.aligned.m16n8k16.row.col.f32.bf16.bf16.f32 "
        "{%0,%1,%2,%3}, {%4,%5,%6,%7}, {%8,%9}, {%0,%1,%2,%3};"
        : "+f"(c[0]), "+f"(c[1]), "+f"(c[2]), "+f"(c[3])
        : "r"(a[0]), "r"(a[1]), "r"(a[2]), "r"(a[3]), "r"(b[0]), "r"(b[1]));
}
__device__ __forceinline__ void cpasync16(uint32_t dst, const void* src, bool ok) {
    asm volatile("cp.async.cg.shared.global [%0], [%1], 16, %2;"
        :: "r"(dst), "l"(src), "r"(ok ? 16 : 0) : "memory");
}
__device__ __forceinline__ void cp_commit() {
    asm volatile("cp.async.commit_group;" ::: "memory");
}
template<int N> __device__ __forceinline__ void cp_waitN() {
    asm volatile("cp.async.wait_group %0;" :: "n"(N) : "memory");
}
__device__ __forceinline__ uint32_t sw64(uint32_t off) {
    return off ^ ((off >> 3) & 0x30);
}

// ---------------- merged prep ----------------
__global__ void k_prep(const float* __restrict__ fc1, const float* __restrict__ img,
                       const float* __restrict__ wemb, const float* __restrict__ fc2,
                       const float* __restrict__ u3, const float* __restrict__ u5,
                       const float* __restrict__ fco,
                       const float* __restrict__ w3, const float* __restrict__ w4,
                       const float* __restrict__ w5,
                       const float* __restrict__ b3, const float* __restrict__ u3b,
                       const float* __restrict__ b4, const float* __restrict__ b5,
                       const float* __restrict__ u5b,
                       const float* __restrict__ fc3, const float* __restrict__ fca,
                       const float* __restrict__ fc3b) {
    const int q1 = CD*CD/4;
    const int q2 = q1 + NP*CD/4;
    const int q3 = q2 + LD*WPAD/4;
    const int q4 = q3 + CD*WPAD/4;
    const int q5 = q4 + CD*CD/4;
    const int q6 = q5 + CD*CD/4;
    const int q7 = q6 + OD*2*CD/4;
    const int q8 = q7 + 3*CD*CD/4;
    const int q9 = q8 + 3*CD;
    const int q10 = q9 + CD;
    const int q11 = q10 + CD;
    int stride = gridDim.x*blockDim.x;
    for (int i = blockIdx.x*blockDim.x + threadIdx.x; i < q11; i += stride) {
        if (i < q1) {
            int e = 4*i;
            split4(*(const float4*)&fc1[e], c_fc1_h, c_fc1_l, e);
        } else if (i < q2) {
            int e = 4*(i - q1);
            split4(*(const float4*)&img[e], c_img_h, c_img_l, e);
        } else if (i < q3) {
            int e = 4*(i - q2);
            int r = e / WPAD, c = e - r*WPAD;
            float4 v = (c < WDIM) ? *(const float4*)&wemb[r*WDIM + c]
                                  : make_float4(0.f, 0.f, 0.f, 0.f);
            split4(v, c_wemb_h, c_wemb_l, e);
        } else if (i < q4) {
            int e = 4*(i - q3);
            int r = e / WPAD, c = e - r*WPAD;
            float4 v = (c < WDIM) ? *(const float4*)&fc2[r*WDIM + c]
                                  : make_float4(0.f, 0.f, 0.f, 0.f);
            split4(v, c_fc2_h, c_fc2_l, e);
        } else if (i < q5) {
            int e = 4*(i - q4);
            split4(*(const float4*)&u3[e], c_u3_h, c_u3_l, e);
        } else if (i < q6) {
            int e = 4*(i - q5);
            split4(*(const float4*)&u5[e], c_u5_h, c_u5_l, e);
        } else if (i < q7) {
            int e = 4*(i - q6);
            split4(*(const float4*)&fco[e], c_fco_h, c_fco_l, e);
        } else if (i < q8) {
            int e = 4*(i - q7);
            int which = e / (CD*CD);
            int rem = e - which*(CD*CD);
            int r = rem >> 10, c = rem & (CD-1);
            const float* w = (which==0) ? w3 : (which==1) ? w4 : w5;
            float4 a = *(const float4*)&w[r*2*CD + c];
            float4 b = *(const float4*)&w[r*2*CD + CD + c];
            split4(make_float4(a.x+b.x, a.y+b.y, a.z+b.z, a.w+b.w),
                   c_wall_h, c_wall_l, e);
        } else if (i < q9) {
            int j = i - q8;
            int which = j >> 10, c = j & (CD-1);
            if (which == 0)      d_ball[c]        = b3[c] + u3b[c];
            else if (which == 1) d_ball[CD + c]   = b4[c] + u3b[c]; // torch bug kept
            else                 d_ball[2*CD + c] = b5[c] + u5b[c];
        } else if (i < q10) {
            int c = i - q9;
            float acc = 0.f;
            #pragma unroll 8
            for (int j = 0; j < CD; ++j) acc += fca[j] * fc3[j*CD + c];
            d_v[c] = acc;
        } else {
            int j = i - q10;
            d_c0p[j] = fc3b[j] * fca[j];
        }
    }
}

// ---------------- tensor GEMM: 128 threads, 4-stage cp.async ring (R13 winner) -------
template<int MODE, int TNN>
__global__ __launch_bounds__(128) void t_gemm(
    const unsigned short* __restrict__ Ah, const unsigned short* __restrict__ Al, int lda,
    const unsigned short* __restrict__ Bh, const unsigned short* __restrict__ Bl, int ldb,
    const unsigned short* __restrict__ A2h, const unsigned short* __restrict__ A2l, int lda2,
    const unsigned short* __restrict__ B2h, const unsigned short* __restrict__ B2l, int ldb2,
    int b2mask, int n2_limit,
    int M, int N, int Kpad,
    const float* __restrict__ bias,
    float* __restrict__ p0, float* __restrict__ p1, float* __restrict__ p2,
    unsigned short* __restrict__ q0, unsigned short* __restrict__ q1,
    float* __restrict__ C, int ldc)
{
    constexpr int JF = TNN/16;
    constexpr int JH = JF/2;
    constexpr int STAGE = 8192 + TNN*128;
    constexpr int BCOPY = TNN*4;
    __shared__ __align__(128) char dsm[4*STAGE];
    uint32_t sbase = smem_to_u32(dsm);

    const int tid = threadIdx.x;
    const int wid = tid >> 5;
    const int lane = tid & 31;
    const int m0 = blockIdx.y * TM;
    const int n0 = blockIdx.x * TNN;
    const int wm = (wid >> 1) * 32;
    const int wn = (wid & 1) * (TNN/2);

    const int qm = lane >> 3, rr = lane & 7;
    const int lrow = (qm & 1)*8 + rr;
    const int lkof = (qm >> 1)*8;

    float acc[2][JF][4];
    #pragma unroll
    for (int i = 0; i < 2; ++i)
        #pragma unroll
        for (int j = 0; j < JF; ++j)
            #pragma unroll
            for (int s = 0; s < 4; ++s) acc[i][j][s] = 0.f;

    const int nst1 = Kpad >> 5;
    const bool do2 = (A2h != nullptr) && (n0 < n2_limit);
    const int nst = do2 ? 2*nst1 : nst1;

    auto stage = [&](int t) {
        int pass = (t >= nst1) ? 1 : 0;
        int k0 = (t - pass*nst1) << 5;
        const unsigned short* pAh = pass ? A2h : Ah;
        const unsigned short* pAl = pass ? A2l : Al;
        const unsigned short* pBh = pass ? B2h : Bh;
        const unsigned short* pBl = pass ? B2l : Bl;
        int la = pass ? lda2 : lda;
        int lb = pass ? ldb2 : ldb;
        int bm = pass ? b2mask : NOMASK;
        uint32_t sb = sbase + (t & 3) * STAGE;
        #pragma unroll
        for (int qq = 0; qq*128 < 512 + 2*BCOPY; ++qq) {
            int c = tid + (qq << 7);
            if (c < 512) {
                int part = c >> 8;
                int sub = c & 255;
                int row = sub >> 2, quad = sub & 3;
                int gr = m0 + row;
                bool ok = gr < M;
                const unsigned short* s = (part ? pAl : pAh)
                                          + (size_t)(ok ? gr : 0)*la + k0 + quad*8;
                uint32_t off = sw64((uint32_t)(row*64 + quad*16));
                cpasync16(sb + part*4096 + off, s, ok);
            } else {
                int cb = c - 512;
                int part = (cb >= BCOPY) ? 1 : 0;
                int sub = cb - part*BCOPY;
                int row = sub >> 2, quad = sub & 3;
                int gn = n0 + row;
                bool ok = gn < N;
                int er = (ok ? gn : 0) & bm;
                const unsigned short* s = (part ? pBl : pBh)
                                          + (size_t)er*lb + k0 + quad*8;
                uint32_t off = sw64((uint32_t)(row*64 + quad*16));
                cpasync16(sb + 8192 + part*(TNN*64) + off, s, ok);
            }
        }
        cp_commit();
    };

    stage(0);
    if (nst > 1) stage(1);
    if (nst > 2) stage(2);
    for (int t = 0; t < nst; ++t) {
        if (t + 2 < nst) cp_waitN<2>();
        else if (t + 1 < nst) cp_waitN<1>();
        else cp_waitN<0>();
        __syncthreads();
        uint32_t sb = sbase + (t & 3) * STAGE;
        uint32_t sa_hi = sb, sa_lo = sb + 4096;
        uint32_t sb_hi = sb + 8192, sb_lo = sb + 8192 + TNN*64;
        #pragma unroll
        for (int k0 = 0; k0 < 32; k0 += 16) {
            uint32_t ah[2][4], al[2][4], bh[JF][2], bl[JF][2];
            #pragma unroll
            for (int i = 0; i < 2; ++i) {
                uint32_t off = sw64((uint32_t)((wm + i*16 + lrow)*64 + (k0 + lkof)*2));
                ldsm_x4(ah[i], sa_hi + off);
                ldsm_x4(al[i], sa_lo + off);
            }
            #pragma unroll
            for (int jh = 0; jh < JH; ++jh) {
                uint32_t off = sw64((uint32_t)((wn + jh*16 + lrow)*64 + (k0 + lkof)*2));
                uint32_t r[4];
                ldsm_x4(r, sb_hi + off);
                bh[2*jh][0]=r[0]; bh[2*jh][1]=r[2]; bh[2*jh+1][0]=r[1]; bh[2*jh+1][1]=r[3];
                ldsm_x4(r, sb_lo + off);
                bl[2*jh][0]=r[0]; bl[2*jh][1]=r[2]; bl[2*jh+1][0]=r[1]; bl[2*jh+1][1]=r[3];
            }
            #pragma unroll
            for (int i = 0; i < 2; ++i)
                #pragma unroll
                for (int j = 0; j < JF; ++j) {
                    mma16816(acc[i][j], ah[i], bh[j]);
                    mma16816(acc[i][j], ah[i], bl[j]);
                    mma16816(acc[i][j], al[i], bh[j]);
                }
        }
        if (t + 3 < nst) stage(t + 3);
    }

    // epilogue (fast transcendentals)
    const int g = lane >> 2, tq = (lane & 3)*2;
    #pragma unroll
    for (int i = 0; i < 2; ++i) {
        #pragma unroll
        for (int half = 0; half < 2; ++half) {
            int m = m0 + wm + i*16 + g + half*8;
            if (m >= M) continue;
            #pragma unroll
            for (int j = 0; j < JF; ++j) {
                #pragma unroll
                for (int s = 0; s < 2; ++s) {
                    int n = n0 + wn + j*8 + tq + s;
                    if (n >= N) continue;
                    float x = acc[i][j][half*2 + s];
                    if (MODE == MODE_NONE) {
                        C[(size_t)m*ldc + n] = x;
                    } else if (MODE == MODE_ZRH) {
                        x += bias[n];
                        if (n < CD) {
                            p0[m*CD + n] = sigf(x);
                        } else if (n < 2*CD) {
                            int nn = n - CD;
                            float rn = sigf(x) * p2[m*CD + nn];
                            split_bf(rn, &q0[m*CD + nn], &q1[m*CD + nn]);
                        } else {
                            p1[m*CD + (n - 2*CD)] = x;
                        }
                    } else if (MODE == MODE_GRU2) {
                        float hc = tanha(x + p1[m*CD + n]);
                        float z  = p0[m*CD + n];
                        float nv = (1.f - z)*p2[m*CD + n] + z*hc;
                        p2[m*CD + n] = nv;
                        split_bf(nv, &q0[m*CD + n], &q1[m*CD + n]);
                    } else { // MODE_TANH
                        C[(size_t)m*ldc + n] = tanha(x + bias[n]);
                    }
                }
            }
        }
    }
}

// ---------------- semantic-branch kernels ----------------
// 2 n-rows per block; v in SMEM + transient c0 regs => ~80 regs => 3 blocks/SM
__global__ __launch_bounds__(256, 3) void k_coeff(const float* __restrict__ fcab) {
    __shared__ float v_s[CD];
    int n0 = blockIdx.x * 2;
    int warp = threadIdx.x >> 5, lane = threadIdx.x & 31;
    for (int i = threadIdx.x; i < CD; i += 256) v_s[i] = d_v[i];
    // c0 via transient loop (per-warp redundant, no reg cache)
    float c0 = 0.f;
    for (int i = lane; i < CD; i += 32) c0 += d_c0p[i];
    #pragma unroll
    for (int o = 16; o > 0; o >>= 1) c0 += __shfl_xor_sync(0xffffffffu, c0, o);
    c0 += fcab[0];
    // cache the two fwh rows in regs
    float fw0[32], fw1[32];
    const float* r0 = d_fwh + n0*CD + lane;
    #pragma unroll
    for (int q = 0; q < 32; ++q) {
        fw0[q] = r0[q*32];
        fw1[q] = r0[CD + q*32];
    }
    __syncthreads();
    for (int l = warp; l < LD; l += 8) {
        const float* fw = d_fwd + l*CD + lane;
        float a0 = 0.f, a1 = 0.f;
        #pragma unroll
        for (int q = 0; q < 32; ++q) {
            float w = fw[q*32];
            float vv = v_s[q*32 + lane];
            a0 += tanha(fw0[q] * w) * vv;
            a1 += tanha(fw1[q] * w) * vv;
        }
        #pragma unroll
        for (int o = 16; o > 0; o >>= 1) {
            a0 += __shfl_xor_sync(0xffffffffu, a0, o);
            a1 += __shfl_xor_sync(0xffffffffu, a1, o);
        }
        if (lane == 0) {
            d_coeff[n0*LD + l]     = a0 + c0;
            d_coeff[(n0+1)*LD + l] = a1 + c0;
        }
    }
}

__global__ __launch_bounds__(256) void k_softmax() {
    int g = blockIdx.x*8 + (threadIdx.x >> 5);
    int lane = threadIdx.x & 31;
    if (g >= NP*LD/HW) return;
    float* p = d_coeff + g*HW;
    float vals[7];
    float mx = -1e30f;
    #pragma unroll
    for (int q = 0; q < 7; ++q) {
        int i = lane + q*32;
        vals[q] = (i < HW) ? p[i] : -1e30f;
        mx = fmaxf(mx, vals[q]);
    }
    #pragma unroll
    for (int o = 16; o > 0; o >>= 1) mx = fmaxf(mx, __shfl_xor_sync(0xffffffffu, mx, o));
    float s = 0.f;
    #pragma unroll
    for (int q = 0; q < 7; ++q) {
        int i = lane + q*32;
        if (i < HW) { vals[q] = __expf(vals[q] - mx); s += vals[q]; }
    }
    #pragma unroll
    for (int o = 16; o > 0; o >>= 1) s += __shfl_xor_sync(0xffffffffu, s, o);
    float inv = __fdividef(1.f, s);
    #pragma unroll
    for (int q = 0; q < 7; ++q) {
        int i = lane + q*32;
        if (i < HW) p[i] = vals[q]*inv;
    }
}

__global__ __launch_bounds__(256) void k_g(const float* __restrict__ img) {
    __shared__ float s[HW];
    int b = blockIdx.x / LD, l = blockIdx.x % LD;
    for (int tt = threadIdx.x; tt < HW; tt += 256)
        s[tt] = d_coeff[(b*HW + tt)*LD + l];
    __syncthreads();
    const float* xb = img + b*HW*CD;
    int c = threadIdx.x;
    float a0 = 0.f, a1 = 0.f, a2 = 0.f, a3 = 0.f;
    #pragma unroll 4
    for (int tt = 0; tt < HW; ++tt) {
        float w = s[tt];
        const float* xr = xb + tt*CD;
        a0 += w*xr[c]; a1 += w*xr[c+256]; a2 += w*xr[c+512]; a3 += w*xr[c+768];
    }
    int base = (b*LD + l)*CD + c;
    float vals[4] = {a0, a1, a2, a3};
    #pragma unroll
    for (int q = 0; q < 4; ++q) {
        int idx = base + q*256;
        d_nodes[idx] = vals[q];
        split_bf(vals[q], &c_g_h[idx], &c_g_l[idx]);
        c_nodes_h[idx] = c_g_h[idx];
        c_nodes_l[idx] = c_g_l[idx];
    }
}

__global__ __launch_bounds__(256) void k_a(const float* __restrict__ adj) {
    __shared__ float ar[LD];
    int b = blockIdx.x / LD, nn = blockIdx.x % LD;
    if (threadIdx.x < LD) ar[threadIdx.x] = adj[nn*LD + threadIdx.x];
    __syncthreads();
    int c = threadIdx.x;
    const float* nb = d_nodes + b*LD*CD;
    float a0 = 0.f, a1 = 0.f, a2 = 0.f, a3 = 0.f;
    #pragma unroll 4
    for (int m = 0; m < LD; ++m) {
        float w = ar[m];
        const float* nr = nb + m*CD;
        a0 += w*nr[c]; a1 += w*nr[c+256]; a2 += w*nr[c+512]; a3 += w*nr[c+768];
    }
    int base = (b*LD + nn)*CD + c;
    float vals[4] = {a0, a1, a2, a3};
    #pragma unroll
    for (int q = 0; q < 4; ++q) {
        int idx = base + q*256;
        split_bf(vals[q], &c_a_h[idx], &c_a_l[idx]);
    }
}

// ---------------- host ----------------
struct Sym {
    float *fwd, *v, *c0p, *ball, *fwh, *coeff, *nodes, *zbuf, *hbuf;
    unsigned short *imgh, *imgl, *fc1h, *fc1l, *wembh, *wembl, *fc2h, *fc2l;
    unsigned short *wallh, *walll, *u3h, *u3l, *u5h, *u5l, *fcoh, *fcol;
    unsigned short *ndh, *ndl, *ah, *al, *rnh, *rnl, *gh, *gl;
};
static void get_syms(Sym& S) {
    cudaGetSymbolAddress((void**)&S.fwd, d_fwd);
    cudaGetSymbolAddress((void**)&S.v, d_v);
    cudaGetSymbolAddress((void**)&S.c0p, d_c0p);
    cudaGetSymbolAddress((void**)&S.ball, d_ball);
    cudaGetSymbolAddress((void**)&S.fwh, d_fwh);
    cudaGetSymbolAddress((void**)&S.coeff, d_coeff);
    cudaGetSymbolAddress((void**)&S.nodes, d_nodes);
    cudaGetSymbolAddress((void**)&S.zbuf, d_zbuf);
    cudaGetSymbolAddress((void**)&S.hbuf, d_hbuf);
    cudaGetSymbolAddress((void**)&S.imgh, c_img_h);   cudaGetSymbolAddress((void**)&S.imgl, c_img_l);
    cudaGetSymbolAddress((void**)&S.fc1h, c_fc1_h);   cudaGetSymbolAddress((void**)&S.fc1l, c_fc1_l);
    cudaGetSymbolAddress((void**)&S.wembh, c_wemb_h); cudaGetSymbolAddress((void**)&S.wembl, c_wemb_l);
    cudaGetSymbolAddress((void**)&S.fc2h, c_fc2_h);   cudaGetSymbolAddress((void**)&S.fc2l, c_fc2_l);
    cudaGetSymbolAddress((void**)&S.wallh, c_wall_h); cudaGetSymbolAddress((void**)&S.walll, c_wall_l);
    cudaGetSymbolAddress((void**)&S.u3h, c_u3_h);     cudaGetSymbolAddress((void**)&S.u3l, c_u3_l);
    cudaGetSymbolAddress((void**)&S.u5h, c_u5_h);     cudaGetSymbolAddress((void**)&S.u5l, c_u5_l);
    cudaGetSymbolAddress((void**)&S.fcoh, c_fco_h);   cudaGetSymbolAddress((void**)&S.fcol, c_fco_l);
    cudaGetSymbolAddress((void**)&S.ndh, c_nodes_h);  cudaGetSymbolAddress((void**)&S.ndl, c_nodes_l);
    cudaGetSymbolAddress((void**)&S.ah, c_a_h);       cudaGetSymbolAddress((void**)&S.al, c_a_l);
    cudaGetSymbolAddress((void**)&S.rnh, c_rn_h);     cudaGetSymbolAddress((void**)&S.rnl, c_rn_l);
    cudaGetSymbolAddress((void**)&S.gh, c_g_h);       cudaGetSymbolAddress((void**)&S.gl, c_g_l);
}

template<int MODE, int TNN>
static void tg(const unsigned short* Ah, const unsigned short* Al, int lda,
               const unsigned short* Bh, const unsigned short* Bl, int ldb,
               const unsigned short* A2h, const unsigned short* A2l, int lda2,
               const unsigned short* B2h, const unsigned short* B2l, int ldb2,
               int b2mask, int n2lim, int M, int N, int Kpad,
               const float* bias, float* p0, float* p1, float* p2,
               unsigned short* q0, unsigned short* q1, float* C, int ldc) {
    dim3 grid((N + TNN - 1)/TNN, (M + TM - 1)/TM);
    t_gemm<MODE, TNN><<<grid, 128>>>(Ah, Al, lda, Bh, Bl, ldb, A2h, A2l, lda2,
                                     B2h, B2l, ldb2, b2mask, n2lim, M, N, Kpad,
                                     bias, p0, p1, p2, q0, q1, C, ldc);
}

extern "C" void kernel_launch(void* const* d_in, const int* in_sizes, int n_in,
                              void* d_out, int out_size) {
    const float* img  = (const float*)d_in[0];
    const float* wemb = (const float*)d_in[1];
    const float* adj  = (const float*)d_in[2];
    const float* fc1  = (const float*)d_in[3];
    const float* fc2  = (const float*)d_in[4];
    const float* fc3  = (const float*)d_in[5];
    const float* fc3b = (const float*)d_in[6];
    const float* fca  = (const float*)d_in[7];
    const float* fcab = (const float*)d_in[8];
    const float* w3   = (const float*)d_in[9];
    const float* b3   = (const float*)d_in[10];
    const float* u3   = (const float*)d_in[11];
    const float* u3b  = (const float*)d_in[12];
    const float* w4   = (const float*)d_in[13];
    const float* b4   = (const float*)d_in[14];
    const float* w5   = (const float*)d_in[15];
    const float* b5   = (const float*)d_in[16];
    const float* u5   = (const float*)d_in[17];
    const float* u5b  = (const float*)d_in[18];
    const float* fco  = (const float*)d_in[19];
    const float* fcob = (const float*)d_in[20];
    float* out = (float*)d_out;

    Sym S; get_syms(S);

    // 1: all prep
    k_prep<<<2048, 256>>>(fc1, img, wemb, fc2, u3, u5, fco,
                          w3, w4, w5, b3, u3b, b4, b5, u5b, fc3, fca, fc3b);
    // 2: f_wd = wemb @ fc2^T
    tg<MODE_NONE, 32>(S.wembh, S.wembl, WPAD, S.fc2h, S.fc2l, WPAD,
                      nullptr, nullptr, 0, nullptr, nullptr, 0, NOMASK, 0,
                      LD, CD, WPAD, nullptr, nullptr, nullptr, nullptr, nullptr, nullptr,
                      S.fwd, CD);
    // 3: f_wh = x @ fc1^T
    tg<MODE_NONE, 32>(S.imgh, S.imgl, CD, S.fc1h, S.fc1l, CD,
                      nullptr, nullptr, 0, nullptr, nullptr, 0, NOMASK, 0,
                      NP, CD, CD, nullptr, nullptr, nullptr, nullptr, nullptr, nullptr,
                      S.fwh, CD);
    // 4-6: semantic chain
    k_coeff<<<NP/2, 256>>>(fcab);
    k_softmax<<<40, 256>>>();
    k_g<<<BT*LD, 256>>>(img);

    // GGNN
    for (int step = 0; step < 3; ++step) {
        k_a<<<BT*LD, 256>>>(adj);
        tg<MODE_ZRH, 32>(S.ah, S.al, CD, S.wallh, S.walll, CD,
                         S.ndh, S.ndl, CD, S.u3h, S.u3l, CD, CD-1, 2*CD,
                         NR, 3*CD, CD, S.ball, S.zbuf, S.hbuf, S.nodes,
                         S.rnh, S.rnl, nullptr, 0);
        tg<MODE_GRU2, 32>(S.rnh, S.rnl, CD, S.u5h, S.u5l, CD,
                          nullptr, nullptr, 0, nullptr, nullptr, 0, NOMASK, 0,
                          NR, CD, CD, nullptr, S.zbuf, S.hbuf, S.nodes,
                          S.ndh, S.ndl, nullptr, 0);
    }

    // out = tanh([nodes, g] @ fco^T + fco_b): dual-K over fco column halves
    tg<MODE_TANH, 32>(S.ndh, S.ndl, CD, S.fcoh, S.fcol, 2*CD,
                      S.gh, S.gl, CD, S.fcoh + CD, S.fcol + CD, 2*CD, NOMASK, NOMASK,
                      NR, OD, CD, fcob, nullptr, nullptr, nullptr, nullptr, nullptr,
                      out, OD);
}